// round 5
// baseline (speedup 1.0000x reference)
#include <cuda_runtime.h>
#include <math.h>

// Problem constants (fixed shapes from reference)
#define TTOK 8192
#define DDIM 2048
#define HDIM 8192
#define NEXP 8

// ---------------------------------------------------------------------------
// Scratch: __device__ globals (no cudaMalloc allowed anywhere)
// ---------------------------------------------------------------------------
__device__ int   g_is64;                 // expert_idxs dtype flag (1 = int64)
__device__ int   g_cnt[NEXP];
__device__ int   g_tok[NEXP * TTOK];
__device__ float g_gate[NEXP * TTOK];
__device__ float g_hbuf[(size_t)TTOK * (size_t)HDIM];  // 268 MB intermediate

// ---------------------------------------------------------------------------
// Packed f32x2 helpers (Blackwell fma.rn.f32x2 -> SASS FFMA2, 2x FFMA rate)
// ---------------------------------------------------------------------------
__device__ __forceinline__ unsigned long long pack2(float lo, float hi) {
    unsigned long long r;
    asm("mov.b64 %0, {%1, %2};" : "=l"(r) : "f"(lo), "f"(hi));
    return r;
}
__device__ __forceinline__ void ffma2(unsigned long long& d,
                                      unsigned long long a,
                                      unsigned long long b) {
    asm("fma.rn.f32x2 %0, %1, %2, %0;" : "+l"(d) : "l"(a), "l"(b));
}
__device__ __forceinline__ void unpack2(unsigned long long v, float& lo, float& hi) {
    asm("mov.b64 {%0, %1}, %2;" : "=f"(lo), "=f"(hi) : "l"(v));
}

// JAX default gelu: approximate=True (tanh form)
__device__ __forceinline__ float gelu_tanh(float v) {
    const float c = 0.7978845608028654f;  // sqrt(2/pi)
    float u = c * (v + 0.044715f * v * v * v);
    return 0.5f * v * (1.0f + tanhf(u));
}

// ---------------------------------------------------------------------------
// Dtype detection for expert_idxs: scan first 8192 int32 pairs. int64 ids in
// [0,8) have all-zero high words; int32 layout puts real expert ids in the odd
// slots (P[all zero by chance] = 8^-8192). In-bounds for either dtype.
// ---------------------------------------------------------------------------
__global__ void k_detect(const int* __restrict__ idx32) {
    __shared__ int odd_nonzero;
    if (threadIdx.x == 0) odd_nonzero = 0;
    __syncthreads();
    int local = 0;
    for (int i = threadIdx.x; i < 8192; i += blockDim.x)
        if (idx32[2 * i + 1] != 0) local = 1;
    if (local) odd_nonzero = 1;
    __syncthreads();
    if (threadIdx.x == 0) g_is64 = (odd_nonzero == 0) ? 1 : 0;
}

// ---------------------------------------------------------------------------
// Routing: build per-expert compacted token lists + merged gates
// ---------------------------------------------------------------------------
__global__ void k_zero_counts() {
    if (threadIdx.x < NEXP) g_cnt[threadIdx.x] = 0;
}

__global__ void k_route(const float* __restrict__ p,
                        const void* __restrict__ idxv) {
    int t = blockIdx.x * blockDim.x + threadIdx.x;
    if (t >= TTOK) return;
    int e0, e1;
    if (g_is64) {
        const long long* q = (const long long*)idxv;
        e0 = (int)q[2 * t + 0];
        e1 = (int)q[2 * t + 1];
    } else {
        const int* q = (const int*)idxv;
        e0 = q[2 * t + 0];
        e1 = q[2 * t + 1];
    }
    float p0 = p[2 * t + 0];
    float p1 = p[2 * t + 1];
    bool ok0 = (e0 >= 0 && e0 < NEXP);
    bool ok1 = (e1 >= 0 && e1 < NEXP);
    if (ok0 && ok1 && e0 == e1) {
        int pos = atomicAdd(&g_cnt[e0], 1);
        g_tok[e0 * TTOK + pos]  = t;
        g_gate[e0 * TTOK + pos] = p0 + p1;
    } else {
        if (ok0) {
            int pos = atomicAdd(&g_cnt[e0], 1);
            g_tok[e0 * TTOK + pos]  = t;
            g_gate[e0 * TTOK + pos] = p0;
        }
        if (ok1) {
            int pos = atomicAdd(&g_cnt[e1], 1);
            g_tok[e1 * TTOK + pos]  = t;
            g_gate[e1 * TTOK + pos] = p1;
        }
    }
}

__global__ void k_zero_out(float4* __restrict__ out) {
    size_t i = (size_t)blockIdx.x * blockDim.x + threadIdx.x;
    out[i] = make_float4(0.f, 0.f, 0.f, 0.f);
}

// ---------------------------------------------------------------------------
// GEMM1: Hbuf[i, :] = gelu( x[tok[i], :] @ W1[e] ),  i < cnt[e]
// 128x128 tile, BK=8, 256 threads, 8x8 per thread, FFMA2 core.
// ---------------------------------------------------------------------------
__global__ void __launch_bounds__(256)
k_gemm1(const float* __restrict__ X, const float* __restrict__ W1, int e) {
    const int cnt = g_cnt[e];
    const int m0 = blockIdx.y * 128;
    if (m0 >= cnt) return;
    const int n0 = blockIdx.x * 128;

    __shared__ float As[8][128];
    __shared__ float Bs[8][128];

    const int tid = threadIdx.x;
    const int tx = tid & 15;   // n sub-tile
    const int ty = tid >> 4;   // m sub-tile

    // A load: 2 threads per row, float4 each (8 k-values per row)
    const int arow = tid >> 1;
    const int acol = (tid & 1) * 4;
    int gi = m0 + arow;                       // always within list bounds
    int tok = g_tok[e * TTOK + gi];           // stale beyond cnt: safe, unused
    const float* aptr = X + (size_t)tok * DDIM + acol;

    // B load: 32 threads per k-row, float4 each
    const int brow = tid >> 5;
    const int bcol = (tid & 31) * 4;
    const float* bptr = W1 + (size_t)brow * HDIM + n0 + bcol;

    unsigned long long acc[8][4];
#pragma unroll
    for (int i = 0; i < 8; i++)
#pragma unroll
        for (int j = 0; j < 4; j++) acc[i][j] = 0ull;

    for (int k0 = 0; k0 < DDIM; k0 += 8) {
        float4 av = *(const float4*)(aptr + k0);
        float4 bv = *(const float4*)(bptr + (size_t)k0 * HDIM);
        __syncthreads();
        As[acol + 0][arow] = av.x;
        As[acol + 1][arow] = av.y;
        As[acol + 2][arow] = av.z;
        As[acol + 3][arow] = av.w;
        *(float4*)&Bs[brow][bcol] = bv;
        __syncthreads();
#pragma unroll
        for (int kk = 0; kk < 8; kk++) {
            float4 a0 = *(const float4*)&As[kk][ty * 8];
            float4 a1 = *(const float4*)&As[kk][ty * 8 + 4];
            float a[8] = {a0.x, a0.y, a0.z, a0.w, a1.x, a1.y, a1.z, a1.w};
            const unsigned long long* b2 =
                (const unsigned long long*)&Bs[kk][tx * 8];
            unsigned long long bl[4];
#pragma unroll
            for (int j = 0; j < 4; j++) bl[j] = b2[j];
#pragma unroll
            for (int i = 0; i < 8; i++) {
                unsigned long long ap = pack2(a[i], a[i]);
#pragma unroll
                for (int j = 0; j < 4; j++) ffma2(acc[i][j], ap, bl[j]);
            }
        }
    }

#pragma unroll
    for (int i = 0; i < 8; i++) {
        int row = m0 + ty * 8 + i;
        if (row < cnt) {
            float r[8];
#pragma unroll
            for (int j = 0; j < 4; j++) {
                float lo, hi;
                unpack2(acc[i][j], lo, hi);
                r[2 * j + 0] = gelu_tanh(lo);
                r[2 * j + 1] = gelu_tanh(hi);
            }
            float4* dst = (float4*)&g_hbuf[(size_t)row * HDIM + n0 + tx * 8];
            dst[0] = make_float4(r[0], r[1], r[2], r[3]);
            dst[1] = make_float4(r[4], r[5], r[6], r[7]);
        }
    }
}

// ---------------------------------------------------------------------------
// GEMM2: Y[tok[i], :] += gate[i] * ( Hbuf[i, :] @ W2[e] )
// Scatter += is race-free: one list entry per token per expert, expert
// kernels serialized on the stream.
// ---------------------------------------------------------------------------
__global__ void __launch_bounds__(256)
k_gemm2(const float* __restrict__ W2, int e, float* __restrict__ Y) {
    const int cnt = g_cnt[e];
    const int m0 = blockIdx.y * 128;
    if (m0 >= cnt) return;
    const int n0 = blockIdx.x * 128;

    __shared__ float As[8][128];
    __shared__ float Bs[8][128];

    const int tid = threadIdx.x;
    const int tx = tid & 15;
    const int ty = tid >> 4;

    const int arow = tid >> 1;
    const int acol = (tid & 1) * 4;
    const float* aptr = g_hbuf + (size_t)(m0 + arow) * HDIM + acol;

    const int brow = tid >> 5;
    const int bcol = (tid & 31) * 4;
    const float* bptr = W2 + (size_t)brow * DDIM + n0 + bcol;

    unsigned long long acc[8][4];
#pragma unroll
    for (int i = 0; i < 8; i++)
#pragma unroll
        for (int j = 0; j < 4; j++) acc[i][j] = 0ull;

    for (int k0 = 0; k0 < HDIM; k0 += 8) {
        float4 av = *(const float4*)(aptr + k0);
        float4 bv = *(const float4*)(bptr + (size_t)k0 * DDIM);
        __syncthreads();
        As[acol + 0][arow] = av.x;
        As[acol + 1][arow] = av.y;
        As[acol + 2][arow] = av.z;
        As[acol + 3][arow] = av.w;
        *(float4*)&Bs[brow][bcol] = bv;
        __syncthreads();
#pragma unroll
        for (int kk = 0; kk < 8; kk++) {
            float4 a0 = *(const float4*)&As[kk][ty * 8];
            float4 a1 = *(const float4*)&As[kk][ty * 8 + 4];
            float a[8] = {a0.x, a0.y, a0.z, a0.w, a1.x, a1.y, a1.z, a1.w};
            const unsigned long long* b2 =
                (const unsigned long long*)&Bs[kk][tx * 8];
            unsigned long long bl[4];
#pragma unroll
            for (int j = 0; j < 4; j++) bl[j] = b2[j];
#pragma unroll
            for (int i = 0; i < 8; i++) {
                unsigned long long ap = pack2(a[i], a[i]);
#pragma unroll
                for (int j = 0; j < 4; j++) ffma2(acc[i][j], ap, bl[j]);
            }
        }
    }

#pragma unroll
    for (int i = 0; i < 8; i++) {
        int row = m0 + ty * 8 + i;
        if (row < cnt) {
            int   t    = g_tok[e * TTOK + row];
            float gate = g_gate[e * TTOK + row];
            float r[8];
#pragma unroll
            for (int j = 0; j < 4; j++) {
                float lo, hi;
                unpack2(acc[i][j], lo, hi);
                r[2 * j + 0] = gate * lo;
                r[2 * j + 1] = gate * hi;
            }
            float4* dst = (float4*)(Y + (size_t)t * DDIM + n0 + tx * 8);
            float4 o0 = dst[0];
            float4 o1 = dst[1];
            o0.x += r[0]; o0.y += r[1]; o0.z += r[2]; o0.w += r[3];
            o1.x += r[4]; o1.y += r[5]; o1.z += r[6]; o1.w += r[7];
            dst[0] = o0;
            dst[1] = o1;
        }
    }
}

// ---------------------------------------------------------------------------
// Launch (graph-capturable: kernel launches only, deterministic)
// ---------------------------------------------------------------------------
extern "C" void kernel_launch(void* const* d_in, const int* in_sizes, int n_in,
                              void* d_out, int out_size) {
    const float* x   = (const float*)d_in[0];
    const float* p   = (const float*)d_in[1];
    const void*  idx = d_in[2];              // int64 OR int32 — detected on device
    const float* w1  = (const float*)d_in[3];
    const float* w2  = (const float*)d_in[4];
    float*       y   = (float*)d_out;

    k_detect<<<1, 256>>>((const int*)idx);
    k_zero_counts<<<1, 32>>>();
    k_route<<<TTOK / 256, 256>>>(p, idx);
    k_zero_out<<<(int)(((size_t)TTOK * DDIM / 4) / 256), 256>>>((float4*)y);

    for (int e = 0; e < NEXP; e++) {
        k_gemm1<<<dim3(HDIM / 128, TTOK / 128), 256>>>(
            x, w1 + (size_t)e * DDIM * HDIM, e);
        k_gemm2<<<dim3(DDIM / 128, TTOK / 128), 256>>>(
            w2 + (size_t)e * HDIM * DDIM, e, y);
    }
}